// round 9
// baseline (speedup 1.0000x reference)
#include <cuda_runtime.h>
#include <cstddef>
#include <cstdint>

#define HW 4096
#define NB 4
#define EPS_ATT 1e-15f
#define NCH 4   // att_ctx N-split chunks

// ---------------- scratch (device globals; no allocation allowed) ----------------
__device__ __align__(16) float g_bufA[NB * 256 * HW];
__device__ __align__(16) float g_bufB[NB * 256 * HW];
__device__ __align__(16) float g_qt[NB * 256 * HW];
__device__ __align__(16) float g_qrgb[NB * 256 * HW];
__device__ __align__(16) float g_qts[NB * 256 * HW];
__device__ __align__(16) float g_qrgbs[NB * 256 * HW];
__device__ __align__(16) float g_qtmp1[NB * 256 * HW];
__device__ __align__(16) float g_qtmp2[NB * 256 * HW];
__device__ __align__(16) float g_kv[NB * 1024 * HW];
__device__ __align__(16) float g_kvtmp[NB * 1024 * HW];
__device__ __align__(16) float g_kvs[NB * 1024 * HW];
__device__ __align__(16) float g_att[NB * 1024 * HW];
__device__ __align__(16) float g_ctxp[2 * NCH * NB * 16 * 32 * 33];
// tf32-rounded, tiled+swizzled weights / rounded inputs
__device__ __align__(16) float g_wrnd[1376256];
__device__ __align__(16) float g_rgbr[NB * 256 * HW];
__device__ __align__(16) float g_tr[NB * 256 * HW];

// rounded-weight offsets (floats)
#define WO_M1INV 0
#define WO_M1PW  131072
#define WO_KV    196608
#define WO_QT    458752
#define WO_QRGB  524288
#define WO_PROJ  589824
#define WO_M2INV 851968
#define WO_M2PW  1114112

__device__ __forceinline__ float hswish_f(float x) {
    return x * fminf(fmaxf(x + 3.0f, 0.0f), 6.0f) * (1.0f / 6.0f);
}

__device__ __forceinline__ unsigned f2tf32(float x) {
    unsigned r;
    asm("cvt.rna.tf32.f32 %0, %1;" : "=r"(r) : "f"(x));
    return r;
}
__device__ __forceinline__ float rnd_tf32(float x) {
    return __uint_as_float(f2tf32(x));
}

__device__ __forceinline__ void mma_tf32(
    float& c0, float& c1, float& c2, float& c3,
    unsigned a0, unsigned a1, unsigned a2, unsigned a3,
    unsigned b0, unsigned b1)
{
    asm volatile(
        "mma.sync.aligned.m16n8k8.row.col.f32.tf32.tf32.f32 "
        "{%0,%1,%2,%3}, {%4,%5,%6,%7}, {%8,%9}, {%0,%1,%2,%3};"
        : "+f"(c0), "+f"(c1), "+f"(c2), "+f"(c3)
        : "r"(a0), "r"(a1), "r"(a2), "r"(a3), "r"(b0), "r"(b1));
}

// ---------------- mbarrier + bulk-async helpers (validated in R8) ----------------
__device__ __forceinline__ void mbar_init(uint32_t mbar, unsigned count) {
    asm volatile("mbarrier.init.shared.b64 [%0], %1;" :: "r"(mbar), "r"(count) : "memory");
}
__device__ __forceinline__ void mbar_expect_tx(uint32_t mbar, unsigned tx) {
    asm volatile("mbarrier.arrive.expect_tx.shared.b64 _, [%0], %1;" :: "r"(mbar), "r"(tx) : "memory");
}
__device__ __forceinline__ void mbar_arrive(uint32_t mbar) {
    asm volatile("mbarrier.arrive.shared.b64 _, [%0];" :: "r"(mbar) : "memory");
}
__device__ __forceinline__ void mbar_wait(uint32_t mbar, int phase) {
    asm volatile(
        "{\n\t.reg .pred P;\n\t"
        "WL_%=:\n\t"
        "mbarrier.try_wait.parity.acquire.cta.shared::cta.b64 P, [%0], %1, 0x989680;\n\t"
        "@!P bra WL_%=;\n\t"
        "}"
        :: "r"(mbar), "r"(phase) : "memory");
}
__device__ __forceinline__ void bulk_g2s(uint32_t dst, const void* src, unsigned bytes, uint32_t mbar) {
    asm volatile(
        "cp.async.bulk.shared::cta.global.mbarrier::complete_tx::bytes [%0], [%1], %2, [%3];"
        :: "r"(dst), "l"(src), "r"(bytes), "r"(mbar) : "memory");
}

// ---------------- pre-pass: round + TILE + SWIZZLE weights into g_wrnd ----------------
// Layout: [mblk (128 rows)][ktile (32 cols)] blocks of 4096 words; within block:
//   word (m_local, k_local) at m_local*32 + ((chunk ^ (m_local&7))<<2) + (k_local&3),
//   chunk = (k_local>>2). One 16KB bulk copy per (mblk, ktile) in the GEMM.
__global__ void __launch_bounds__(256) round_weights(
    const float* __restrict__ w0, const float* __restrict__ w1,
    const float* __restrict__ w2, const float* __restrict__ w3,
    const float* __restrict__ w4, const float* __restrict__ w5,
    const float* __restrict__ w6, const float* __restrict__ w7,
    float* __restrict__ wr)
{
    const float* src; int off; int Cin; int len;
    switch (blockIdx.z) {
        case 0: src = w0; off = WO_M1INV; Cin = 512;  len = 131072; break;
        case 1: src = w1; off = WO_M1PW;  Cin = 256;  len = 65536;  break;
        case 2: src = w2; off = WO_KV;    Cin = 256;  len = 262144; break;
        case 3: src = w3; off = WO_QT;    Cin = 256;  len = 65536;  break;
        case 4: src = w4; off = WO_QRGB;  Cin = 256;  len = 65536;  break;
        case 5: src = w5; off = WO_PROJ;  Cin = 1024; len = 262144; break;
        case 6: src = w6; off = WO_M2INV; Cin = 256;  len = 262144; break;
        default: src = w7; off = WO_M2PW; Cin = 1024; len = 262144; break;
    }
    const int i = (blockIdx.x * 256 + threadIdx.x) * 4;
    if (i < len) {
        float4 v = *reinterpret_cast<const float4*>(src + i);
        uint4 u;
        u.x = f2tf32(v.x); u.y = f2tf32(v.y); u.z = f2tf32(v.z); u.w = f2tf32(v.w);
        const int m = i / Cin;
        const int k = i - m * Cin;
        const int blk = (m >> 7) * (Cin >> 5) + (k >> 5);
        const int dst = off + blk * 4096 + (m & 127) * 32
                      + ((((k >> 2) & 7) ^ (m & 7)) << 2);
        *reinterpret_cast<uint4*>(wr + dst) = u;
    }
}

// ---------------- pre-pass: round rgb/t to tf32 copies ----------------
__global__ void __launch_bounds__(256) round_inputs(
    const float* __restrict__ rgb, const float* __restrict__ t,
    float* __restrict__ rgbr, float* __restrict__ tr)
{
    const float* src = blockIdx.z ? t : rgb;
    float* dst = blockIdx.z ? tr : rgbr;
    const int i = (blockIdx.x * 256 + threadIdx.x) * 4;
    float4 v = *reinterpret_cast<const float4*>(src + i);
    v.x = rnd_tf32(v.x); v.y = rnd_tf32(v.y); v.z = rnd_tf32(v.z); v.w = rnd_tf32(v.w);
    *reinterpret_cast<float4*>(dst + i) = v;
}

// ---------------- 1x1 conv as TF32 GEMM: tiled-W bulk + mbarrier ring ----------
// Block tile 128(M) x 256(N) x 32(K); 512 threads = 16 warps (2M x 8N), warp 64x32.
// W smem: pre-swizzled 4096-word block, ONE 16KB bulk per tile.
// X smem: [k][n] rows padded to 264 words, 32 x 1KB bulks per tile.
// 3-stage ring; producers: warp0 lane0 (W), warp1 lane0 (X). full: 2 arrivals +
// 49152B tx; empty: 16 warp arrivals.
#define NSTG 3
#define WSTGW 4096
#define XPAD 264
#define XSTGW (32 * XPAD)     // 8448 words
#define GEMM_SMEM (NSTG * (WSTGW + XSTGW) * 4 + 64)
template <int ACT, int ROUND>
__global__ void __launch_bounds__(512, 1) gemm1x1(
    const float* __restrict__ inA, const float* __restrict__ inB,
    int CA, int CB,
    const float* __restrict__ W,          // tiled+swizzled base (wr + off)
    const float* __restrict__ gamma, const float* __restrict__ beta,
    float* __restrict__ out, int Cout)
{
    extern __shared__ __align__(16) float dsm[];
    float* Wsm = dsm;                          // [NSTG][WSTGW]
    float* Xsm = dsm + NSTG * WSTGW;           // [NSTG][XSTGW]
    const uint32_t mbar0 =
        (uint32_t)__cvta_generic_to_shared(dsm + NSTG * (WSTGW + XSTGW));
    // full(s) = mbar0 + s*16 ; empty(s) = mbar0 + s*16 + 8

    const int b    = blockIdx.z;
    const int p0   = blockIdx.x * 256;
    const int mblk = blockIdx.y;
    const int Cin  = CA + CB;
    const int Ktiles = Cin >> 5;
    const int tid  = threadIdx.x;
    const int lane = tid & 31;
    const int warp = tid >> 5;
    const int wm = (warp >> 3) * 64;      // 0 or 64
    const int wn = (warp & 7) * 32;       // 0..224
    const int l4  = lane & 3;
    const int l28 = lane >> 2;

    if (tid == 0) {
#pragma unroll
        for (int s = 0; s < NSTG; s++) {
            mbar_init(mbar0 + s * 16, 2);        // full: W + X producer (+tx)
            mbar_init(mbar0 + s * 16 + 8, 16);   // empty: 16 warp arrivals
        }
        asm volatile("fence.proxy.async.shared::cta;" ::: "memory");
    }
    __syncthreads();

    const bool is_prod = (lane == 0) && (warp < 2);
    int pc_s = 0, pc_ph = 1;   // producer cursor (phase 1: first empty-wait passes)
    int cc_s = 0, cc_ph = 0;   // consumer cursor

    float acc[4][4][4];
#pragma unroll
    for (int i = 0; i < 4; i++)
#pragma unroll
        for (int j = 0; j < 4; j++)
#pragma unroll
            for (int r = 0; r < 4; r++) acc[i][j][r] = 0.0f;

    auto produce = [&](int t) {
        const int s = pc_s;
        const uint32_t fullb = mbar0 + s * 16;
        mbar_wait(mbar0 + s * 16 + 8, pc_ph);   // wait empty
        if (warp == 0) {
            mbar_expect_tx(fullb, 16384);
            uint32_t dst = (uint32_t)__cvta_generic_to_shared(Wsm + s * WSTGW);
            const float* src = W + ((size_t)mblk * Ktiles + t) * 4096;
            bulk_g2s(dst, src, 16384, fullb);
        } else {
            mbar_expect_tx(fullb, 32768);
            uint32_t dst = (uint32_t)__cvta_generic_to_shared(Xsm + s * XSTGW);
            const int k0 = t << 5;
#pragma unroll 4
            for (int k = 0; k < 32; k++) {
                const int ci = k0 + k;
                const float* src = (ci < CA)
                    ? inA + ((size_t)b * CA + ci) * HW + p0
                    : inB + ((size_t)b * CB + (ci - CA)) * HW + p0;
                bulk_g2s(dst, src, 1024, fullb);
                dst += XPAD * 4;
            }
        }
        if (++pc_s == NSTG) { pc_s = 0; pc_ph ^= 1; }
    };

    auto compute = [&](int s) {
        const unsigned* Ws = reinterpret_cast<const unsigned*>(Wsm + s * WSTGW);
        const unsigned* Xs = reinterpret_cast<const unsigned*>(Xsm + s * XSTGW);
#pragma unroll
        for (int kb = 0; kb < 4; kb++) {
            const int kc = kb * 8;
            const int xc0 = (((2 * kb) ^ l28) << 2) + l4;
            const int xc1 = (((2 * kb + 1) ^ l28) << 2) + l4;
            unsigned af[4][4];
            unsigned bf[4][2];
#pragma unroll
            for (int mt = 0; mt < 4; mt++) {
                const int ma = wm + mt * 16 + l28;
                af[mt][0] = Ws[ma * 32 + xc0];
                af[mt][1] = Ws[(ma + 8) * 32 + xc0];
                af[mt][2] = Ws[ma * 32 + xc1];
                af[mt][3] = Ws[(ma + 8) * 32 + xc1];
            }
#pragma unroll
            for (int nt = 0; nt < 4; nt++) {
                const int nb = wn + nt * 8 + l28;
                bf[nt][0] = Xs[(kc + l4) * XPAD + nb];
                bf[nt][1] = Xs[(kc + l4 + 4) * XPAD + nb];
            }
#pragma unroll
            for (int mt = 0; mt < 4; mt++)
#pragma unroll
                for (int nt = 0; nt < 4; nt++)
                    mma_tf32(acc[mt][nt][0], acc[mt][nt][1], acc[mt][nt][2], acc[mt][nt][3],
                             af[mt][0], af[mt][1], af[mt][2], af[mt][3],
                             bf[nt][0], bf[nt][1]);
        }
    };

    const int T = Ktiles;
    if (is_prod) {
        produce(0);
        if (T > 1) produce(1);
        if (T > 2) produce(2);
    }
    for (int t = 0; t < T; t++) {
        mbar_wait(mbar0 + cc_s * 16, cc_ph);    // wait full
        compute(cc_s);
        __syncwarp();
        if (lane == 0) mbar_arrive(mbar0 + cc_s * 16 + 8);   // arrive empty
        if (++cc_s == NSTG) { cc_s = 0; cc_ph ^= 1; }
        if (is_prod && t + NSTG < T) produce(t + NSTG);
    }

    // epilogue
#pragma unroll
    for (int mt = 0; mt < 4; mt++) {
#pragma unroll
        for (int rr = 0; rr < 2; rr++) {
            const int co = mblk * 128 + wm + mt * 16 + l28 + rr * 8;
            const float g  = gamma ? gamma[co] : 1.0f;
            const float be = beta  ? beta[co]  : 0.0f;
            float* orow = out + ((size_t)b * Cout + co) * HW + p0 + wn + l4 * 2;
#pragma unroll
            for (int nt = 0; nt < 4; nt++) {
                float v0 = acc[mt][nt][rr * 2 + 0] * g + be;
                float v1 = acc[mt][nt][rr * 2 + 1] * g + be;
                if (ACT == 1) { v0 = hswish_f(v0); v1 = hswish_f(v1); }
                if (ROUND == 1) { v0 = rnd_tf32(v0); v1 = rnd_tf32(v1); }
                *reinterpret_cast<float2*>(&orow[nt * 8]) = make_float2(v0, v1);
            }
        }
    }
}

// ---------------- grouped 1x1 conv: per-group 32x32 GEMM, 128-pixel tiles ----------------
__global__ void __launch_bounds__(256) grouped_pw(
    const float* __restrict__ in, const float* __restrict__ W,
    float* __restrict__ out, int C)
{
    __shared__ __align__(16) float Wg[32][32];
    __shared__ __align__(16) float Xs[32][128];

    const int b  = blockIdx.z;
    const int g  = blockIdx.y;
    const int p0 = blockIdx.x * 128;
    const int tid = threadIdx.x;

    {
        const int co = tid >> 3;
        const int k  = (tid & 7) << 2;
        float4 w = *reinterpret_cast<const float4*>(&W[(size_t)(g * 32 + co) * 32 + k]);
        Wg[k + 0][co] = w.x; Wg[k + 1][co] = w.y; Wg[k + 2][co] = w.z; Wg[k + 3][co] = w.w;
    }
    {
        const int r = tid >> 5;
        const int c = (tid & 31) << 2;
#pragma unroll
        for (int rr = r; rr < 32; rr += 8) {
            *reinterpret_cast<float4*>(&Xs[rr][c]) =
                *reinterpret_cast<const float4*>(&in[((size_t)b * C + g * 32 + rr) * HW + p0 + c]);
        }
    }
    __syncthreads();

    const int ty = tid >> 5;
    const int tx = tid & 31;
    float acc[4][4];
#pragma unroll
    for (int i = 0; i < 4; i++)
#pragma unroll
        for (int j = 0; j < 4; j++) acc[i][j] = 0.0f;

#pragma unroll
    for (int k = 0; k < 32; k++) {
        float4 a = *reinterpret_cast<const float4*>(&Wg[k][ty * 4]);
        float4 x = *reinterpret_cast<const float4*>(&Xs[k][tx * 4]);
        float av[4] = {a.x, a.y, a.z, a.w};
        float xv[4] = {x.x, x.y, x.z, x.w};
#pragma unroll
        for (int i = 0; i < 4; i++)
#pragma unroll
            for (int j = 0; j < 4; j++)
                acc[i][j] += av[i] * xv[j];
    }

#pragma unroll
    for (int i = 0; i < 4; i++) {
        float* o = out + ((size_t)b * C + g * 32 + ty * 4 + i) * HW + p0 + tx * 4;
        *reinterpret_cast<float4*>(o) = make_float4(acc[i][0], acc[i][1], acc[i][2], acc[i][3]);
    }
}

// ---------------- depthwise KxK conv, full 64x64 image per block, float4 I/O ----------
template <int KS, int ACT, int ROUND>
__global__ void __launch_bounds__(256) dwconv(
    const float* __restrict__ in, const float* __restrict__ w,
    const float* __restrict__ gamma, const float* __restrict__ beta,
    float* __restrict__ out, int C)
{
    const int R = KS / 2;
    __shared__ __align__(16) float tile[68][72];   // data at rows R.., cols 4..
    __shared__ float wsm[25];

    const int ch = blockIdx.x;
    const int b  = blockIdx.y;
    const int tid = threadIdx.x;

    if (tid < KS * KS) wsm[tid] = w[(size_t)ch * KS * KS + tid];

    const int ROWS = 64 + 2 * R;
    for (int idx = tid; idx < ROWS * 18; idx += 256)
        *reinterpret_cast<float4*>(&tile[idx / 18][(idx % 18) * 4]) = make_float4(0.f, 0.f, 0.f, 0.f);
    __syncthreads();

    const float* src = in + ((size_t)b * C + ch) * HW;
#pragma unroll
    for (int i = 0; i < 4; i++) {
        const int idx = tid + i * 256;
        const int y  = idx >> 4;
        const int xq = (idx & 15) << 2;
        *reinterpret_cast<float4*>(&tile[y + R][4 + xq]) =
            *reinterpret_cast<const float4*>(&src[y * 64 + xq]);
    }
    __syncthreads();

    const float g  = gamma ? gamma[ch] : 1.0f;
    const float be = beta  ? beta[ch]  : 0.0f;
    const int oy0 = (tid >> 4) << 2;
    const int ox  = (tid & 15) << 2;
    float* dst = out + ((size_t)b * C + ch) * HW;

#pragma unroll
    for (int ry = 0; ry < 4; ry++) {
        const int oy = oy0 + ry;
        float o[4] = {0.f, 0.f, 0.f, 0.f};
#pragma unroll
        for (int dy = 0; dy < KS; dy++)
#pragma unroll
            for (int dx = 0; dx < KS; dx++) {
                const float wv = wsm[dy * KS + dx];
                const int colb = 4 - R + ox + dx;
#pragma unroll
                for (int j = 0; j < 4; j++)
                    o[j] += wv * tile[oy + dy][colb + j];
            }
        float v[4];
#pragma unroll
        for (int j = 0; j < 4; j++) {
            float r = o[j] * g + be;
            if (ACT == 1) r = hswish_f(r);
            if (ROUND == 1) r = rnd_tf32(r);
            v[j] = r;
        }
        *reinterpret_cast<float4*>(&dst[oy * 64 + ox]) = make_float4(v[0], v[1], v[2], v[3]);
    }
}

// ---------------- attention phase 1 (N-split partials) ----------
__global__ void __launch_bounds__(256) att_ctx(
    const float* __restrict__ kv, const float* __restrict__ kvs,
    float* __restrict__ ctxp)
{
    const int h = blockIdx.x;
    const int b = blockIdx.y;
    const int z = blockIdx.z;          // a*NCH + chunk
    const int a = z >> 2;
    const int chunk = z & (NCH - 1);
    const int hb = h & 7;
    const float* base  = (h < 8) ? kv : kvs;
    const float* kbase = base + ((size_t)b * 1024 + a * 512 + hb * 64) * HW;
    const float* vbase = kbase + (size_t)32 * HW;

    __shared__ __align__(16) float Ksm[128][33];
    __shared__ __align__(16) float Vsm[128][33];

    const int tid = threadIdx.x;
    const int d  = tid & 31;
    const int gq = tid >> 5;

    float acc0 = 0.f, acc1 = 0.f, acc2 = 0.f, acc3 = 0.f, acc4 = 0.f;

    const int nlo = chunk * (HW / NCH);
    const int nhi = nlo + (HW / NCH);
    for (int n0 = nlo; n0 < nhi; n0 += 128) {
        __syncthreads();
#pragma unroll
        for (int i = 0; i < 4; i++) {
            const int idx = tid + i * 256;
            const int ch = idx >> 5;
            const int nq = (idx & 31) << 2;
            float4 kx = *reinterpret_cast<const float4*>(&kbase[(size_t)ch * HW + n0 + nq]);
            float4 vx = *reinterpret_cast<const float4*>(&vbase[(size_t)ch * HW + n0 + nq]);
            Ksm[nq + 0][ch] = fmaxf(kx.x, 0.f);
            Ksm[nq + 1][ch] = fmaxf(kx.y, 0.f);
            Ksm[nq + 2][ch] = fmaxf(kx.z, 0.f);
            Ksm[nq + 3][ch] = fmaxf(kx.w, 0.f);
            Vsm[nq + 0][ch] = vx.x;
            Vsm[nq + 1][ch] = vx.y;
            Vsm[nq + 2][ch] = vx.z;
            Vsm[nq + 3][ch] = vx.w;
        }
        __syncthreads();
#pragma unroll 4
        for (int nn = 0; nn < 128; nn++) {
            const float kd = Ksm[nn][d];
            acc0 += kd * Vsm[nn][gq];
            acc1 += kd * Vsm[nn][gq + 8];
            acc2 += kd * Vsm[nn][gq + 16];
            acc3 += kd * Vsm[nn][gq + 24];
            if (gq == 0) acc4 += kd;
        }
    }

    float* cbase = ctxp + ((((size_t)z * NB + b) * 16 + h) * 32 + d) * 33;
    cbase[gq]      = acc0;
    cbase[gq + 8]  = acc1;
    cbase[gq + 16] = acc2;
    cbase[gq + 24] = acc3;
    if (gq == 0) cbase[32] = acc4;
}

// ---------------- attention phase 2 (sums NCH ctx partials; tf32-rounded output) --------
__global__ void __launch_bounds__(128) att_out(
    const float* __restrict__ qt, const float* __restrict__ qts,
    const float* __restrict__ qrgb, const float* __restrict__ qrgbs,
    const float* __restrict__ ctxp, float* __restrict__ out)
{
    const int n0 = blockIdx.x * 128;
    const int h  = blockIdx.y;
    const int a  = blockIdx.z >> 2;
    const int b  = blockIdx.z & 3;
    const int hb = h & 7;

    const float* q = (a == 0) ? ((h < 8) ? qt : qts) : ((h < 8) ? qrgb : qrgbs);
    q += ((size_t)b * 256 + hb * 32) * HW;

    __shared__ __align__(16) float Qsm[128][33];
    __shared__ __align__(16) float Csm[32 * 33];
    __shared__ __align__(16) float Osm[32][132];   // 132-stride: 16B-divisible rows

    const int tid = threadIdx.x;
#pragma unroll
    for (int i = 0; i < 8; i++) {
        const int idx = tid + i * 128;
        const int ch = idx >> 5;
        const int nq = (idx & 31) << 2;
        float4 x = *reinterpret_cast<const float4*>(&q[(size_t)ch * HW + n0 + nq]);
        Qsm[nq + 0][ch] = fmaxf(x.x, 0.f);
        Qsm[nq + 1][ch] = fmaxf(x.y, 0.f);
        Qsm[nq + 2][ch] = fmaxf(x.z, 0.f);
        Qsm[nq + 3][ch] = fmaxf(x.w, 0.f);
    }
    {
        const float* cb0 = ctxp + ((((size_t)(a * NCH + 0) * NB + b) * 16 + h) * 32) * 33;
        const float* cb1 = ctxp + ((((size_t)(a * NCH + 1) * NB + b) * 16 + h) * 32) * 33;
        const float* cb2 = ctxp + ((((size_t)(a * NCH + 2) * NB + b) * 16 + h) * 32) * 33;
        const float* cb3 = ctxp + ((((size_t)(a * NCH + 3) * NB + b) * 16 + h) * 32) * 33;
        for (int idx = tid; idx < 32 * 33; idx += 128)
            Csm[idx] = cb0[idx] + cb1[idx] + cb2[idx] + cb3[idx];
    }
    __syncthreads();

    float acc[33];
#pragma unroll
    for (int e = 0; e < 33; e++) acc[e] = 0.0f;

#pragma unroll 4
    for (int dd = 0; dd < 32; dd++) {
        const float qd = Qsm[tid][dd];
#pragma unroll
        for (int e = 0; e < 33; e++)
            acc[e] += qd * Csm[dd * 33 + e];
    }
    const float inv = 1.0f / (acc[32] + EPS_ATT);
#pragma unroll
    for (int dd = 0; dd < 32; dd++) Osm[dd][tid] = rnd_tf32(acc[dd] * inv);
    __syncthreads();

    float* ob = out + ((size_t)b * 1024 + a * 512 + h * 32) * HW + n0;
#pragma unroll
    for (int i = 0; i < 8; i++) {
        const int idx = tid + i * 128;
        const int dd = idx >> 5;
        const int nq = (idx & 31) << 2;
        *reinterpret_cast<float4*>(&ob[(size_t)dd * HW + nq]) =
            *reinterpret_cast<const float4*>(&Osm[dd][nq]);
    }
}

// ---------------------------------- launcher ----------------------------------
extern "C" void kernel_launch(void* const* d_in, const int* in_sizes, int n_in,
                              void* d_out, int out_size)
{
    const float* rgb        = (const float*)d_in[0];
    const float* t_in       = (const float*)d_in[1];
    const float* m1_inv_w   = (const float*)d_in[2];
    const float* m1_inv_g   = (const float*)d_in[3];
    const float* m1_inv_b   = (const float*)d_in[4];
    const float* m1_dw_w    = (const float*)d_in[5];
    const float* m1_dw_g    = (const float*)d_in[6];
    const float* m1_dw_b    = (const float*)d_in[7];
    const float* m1_pw_w    = (const float*)d_in[8];
    const float* m1_pw_g    = (const float*)d_in[9];
    const float* m1_pw_b    = (const float*)d_in[10];
    const float* kv_w       = (const float*)d_in[11];
    const float* qrgb_w     = (const float*)d_in[12];
    const float* qt_w       = (const float*)d_in[13];
    const float* agg_kv_dw  = (const float*)d_in[14];
    const float* agg_kv_pw  = (const float*)d_in[15];
    const float* agg_t_dw   = (const float*)d_in[16];
    const float* agg_t_pw   = (const float*)d_in[17];
    const float* agg_rgb_dw = (const float*)d_in[18];
    const float* agg_rgb_pw = (const float*)d_in[19];
    const float* proj_w     = (const float*)d_in[20];
    const float* m2_inv_w   = (const float*)d_in[21];
    const float* m2_inv_bias= (const float*)d_in[22];
    const float* m2_dw_w    = (const float*)d_in[23];
    const float* m2_dw_bias = (const float*)d_in[24];
    const float* m2_pw_w    = (const float*)d_in[25];
    const float* m2_pw_g    = (const float*)d_in[26];
    const float* m2_pw_b    = (const float*)d_in[27];

    void* p;
    cudaGetSymbolAddress(&p, g_bufA);  float* bufA  = (float*)p;
    cudaGetSymbolAddress(&p, g_bufB);  float* bufB  = (float*)p;
    cudaGetSymbolAddress(&p, g_qt);    float* qtb   = (float*)p;
    cudaGetSymbolAddress(&p, g_qrgb);  float* qrgbb = (float*)p;
    cudaGetSymbolAddress(&p, g_qts);   float* qtsb  = (float*)p;
    cudaGetSymbolAddress(&p, g_qrgbs); float* qrgbsb= (float*)p;
    cudaGetSymbolAddress(&p, g_qtmp1); float* qtmp1 = (float*)p;
    cudaGetSymbolAddress(&p, g_qtmp2); float* qtmp2 = (float*)p;
    cudaGetSymbolAddress(&p, g_kv);    float* kvb   = (float*)p;
    cudaGetSymbolAddress(&p, g_kvtmp); float* kvtmp = (float*)p;
    cudaGetSymbolAddress(&p, g_kvs);   float* kvsb  = (float*)p;
    cudaGetSymbolAddress(&p, g_att);   float* attb  = (float*)p;
    cudaGetSymbolAddress(&p, g_ctxp);  float* ctxpb = (float*)p;
    cudaGetSymbolAddress(&p, g_wrnd);  float* wr    = (float*)p;
    cudaGetSymbolAddress(&p, g_rgbr);  float* rgbr  = (float*)p;
    cudaGetSymbolAddress(&p, g_tr);    float* tr    = (float*)p;

    const int SMEM = GEMM_SMEM;   // ~147 KB -> 1 CTA/SM, 16 warps
    cudaFuncSetAttribute(gemm1x1<0,0>, cudaFuncAttributeMaxDynamicSharedMemorySize, SMEM);
    cudaFuncSetAttribute(gemm1x1<0,1>, cudaFuncAttributeMaxDynamicSharedMemorySize, SMEM);
    cudaFuncSetAttribute(gemm1x1<1,0>, cudaFuncAttributeMaxDynamicSharedMemorySize, SMEM);
    cudaFuncSetAttribute(gemm1x1<1,1>, cudaFuncAttributeMaxDynamicSharedMemorySize, SMEM);

    // side stream + fork/join events (host resources, created once)
    static cudaStream_t s1 = nullptr;
    static cudaEvent_t evFork = nullptr, evJoin = nullptr;
    if (s1 == nullptr) {
        cudaStreamCreateWithFlags(&s1, cudaStreamNonBlocking);
        cudaEventCreateWithFlags(&evFork, cudaEventDisableTiming);
        cudaEventCreateWithFlags(&evJoin, cudaEventDisableTiming);
    }

    // pre-round weights (tiled+swizzled) + inputs
    round_weights<<<dim3(256, 1, 8), 256>>>(m1_inv_w, m1_pw_w, kv_w, qt_w, qrgb_w,
                                            proj_w, m2_inv_w, m2_pw_w, wr);
    round_inputs<<<dim3(4096, 1, 2), 256>>>(rgb, t_in, rgbr, tr);

    const dim3 g256(16, 2, NB);     // Cout=256, N-tile 256
    const dim3 g1024(16, 8, NB);    // Cout=1024

    // ---- fork: q-path (independent of m1/kv chain) runs on s1 ----
    cudaEventRecord(evFork, 0);
    cudaStreamWaitEvent(s1, evFork, 0);

    gemm1x1<0,0><<<g256, 512, SMEM, s1>>>(tr, nullptr, 256, 0, wr + WO_QT, nullptr, nullptr, qtb, 256);
    gemm1x1<0,0><<<g256, 512, SMEM, s1>>>(rgbr, nullptr, 256, 0, wr + WO_QRGB, nullptr, nullptr, qrgbb, 256);
    dwconv<5, 0, 0><<<dim3(256, NB), 256, 0, s1>>>(qtb, agg_t_dw, nullptr, nullptr, qtmp1, 256);
    grouped_pw<<<dim3(32, 8, NB), 256, 0, s1>>>(qtmp1, agg_t_pw, qtsb, 256);
    dwconv<5, 0, 0><<<dim3(256, NB), 256, 0, s1>>>(qrgbb, agg_rgb_dw, nullptr, nullptr, qtmp2, 256);
    grouped_pw<<<dim3(32, 8, NB), 256, 0, s1>>>(qtmp2, agg_rgb_pw, qrgbsb, 256);
    cudaEventRecord(evJoin, s1);

    // ---- main chain: m1 bottleneck -> kv -> aggregation -> att_ctx ----
    gemm1x1<1,0><<<g256, 512, SMEM>>>(rgbr, tr, 256, 256, wr + WO_M1INV, m1_inv_g, m1_inv_b, bufA, 256);
    dwconv<3, 1, 1><<<dim3(256, NB), 256>>>(bufA, m1_dw_w, m1_dw_g, m1_dw_b, bufB, 256);
    gemm1x1<0,1><<<g256, 512, SMEM>>>(bufB, nullptr, 256, 0, wr + WO_M1PW, m1_pw_g, m1_pw_b, bufA, 256);
    gemm1x1<0,0><<<g1024, 512, SMEM>>>(bufA, nullptr, 256, 0, wr + WO_KV, nullptr, nullptr, kvb, 1024);
    dwconv<5, 0, 0><<<dim3(1024, NB), 256>>>(kvb, agg_kv_dw, nullptr, nullptr, kvtmp, 1024);
    grouped_pw<<<dim3(32, 32, NB), 256>>>(kvtmp, agg_kv_pw, kvsb, 1024);
    att_ctx<<<dim3(16, NB, 2 * NCH), 256>>>(kvb, kvsb, ctxpb);

    // ---- join, then attention output + m2 chain ----
    cudaStreamWaitEvent(0, evJoin, 0);
    att_out<<<dim3(32, 16, 2 * NB), 128>>>(qtb, qtsb, qrgbb, qrgbsb, ctxpb, attb);

    gemm1x1<0,1><<<g256, 512, SMEM>>>(attb, nullptr, 1024, 0, wr + WO_PROJ, nullptr, nullptr, bufA, 256);
    gemm1x1<1,0><<<g1024, 512, SMEM>>>(bufA, nullptr, 256, 0, wr + WO_M2INV, nullptr, m2_inv_bias, kvtmp, 1024);
    dwconv<3, 1, 1><<<dim3(1024, NB), 256>>>(kvtmp, m2_dw_w, nullptr, m2_dw_bias, kvsb, 1024);
    gemm1x1<0,0><<<g256, 512, SMEM>>>(kvsb, nullptr, 1024, 0, wr + WO_M2PW, m2_pw_g, m2_pw_b, (float*)d_out, 256);
}

// round 10
// speedup vs baseline: 1.1845x; 1.1845x over previous
#include <cuda_runtime.h>
#include <cstddef>

#define HW 4096
#define NB 4
#define EPS_ATT 1e-15f
#define NCH 8   // att_ctx N-split chunks

// ---------------- scratch (device globals; no allocation allowed) ----------------
__device__ __align__(16) float g_bufA[NB * 256 * HW];
__device__ __align__(16) float g_bufB[NB * 256 * HW];
__device__ __align__(16) float g_qt[NB * 256 * HW];
__device__ __align__(16) float g_qrgb[NB * 256 * HW];
__device__ __align__(16) float g_qts[NB * 256 * HW];
__device__ __align__(16) float g_qrgbs[NB * 256 * HW];
__device__ __align__(16) float g_qtmp1[NB * 256 * HW];
__device__ __align__(16) float g_qtmp2[NB * 256 * HW];
__device__ __align__(16) float g_kv[NB * 1024 * HW];
__device__ __align__(16) float g_kvtmp[NB * 1024 * HW];
__device__ __align__(16) float g_kvs[NB * 1024 * HW];
__device__ __align__(16) float g_att[NB * 1024 * HW];
__device__ __align__(16) float g_ctxp[2 * NCH * NB * 16 * 32 * 33];
// tf32-rounded copies
__device__ __align__(16) float g_wrnd[1376256];
__device__ __align__(16) float g_rgbr[NB * 256 * HW];
__device__ __align__(16) float g_tr[NB * 256 * HW];

// rounded-weight offsets (floats)
#define WO_M1INV 0
#define WO_M1PW  131072
#define WO_KV    196608
#define WO_QT    458752
#define WO_QRGB  524288
#define WO_PROJ  589824
#define WO_M2INV 851968
#define WO_M2PW  1114112

__device__ __forceinline__ float hswish_f(float x) {
    return x * fminf(fmaxf(x + 3.0f, 0.0f), 6.0f) * (1.0f / 6.0f);
}

__device__ __forceinline__ unsigned f2tf32(float x) {
    unsigned r;
    asm("cvt.rna.tf32.f32 %0, %1;" : "=r"(r) : "f"(x));
    return r;
}
__device__ __forceinline__ float rnd_tf32(float x) {
    return __uint_as_float(f2tf32(x));
}

__device__ __forceinline__ void mma_tf32(
    float& c0, float& c1, float& c2, float& c3,
    unsigned a0, unsigned a1, unsigned a2, unsigned a3,
    unsigned b0, unsigned b1)
{
    asm volatile(
        "mma.sync.aligned.m16n8k8.row.col.f32.tf32.tf32.f32 "
        "{%0,%1,%2,%3}, {%4,%5,%6,%7}, {%8,%9}, {%0,%1,%2,%3};"
        : "+f"(c0), "+f"(c1), "+f"(c2), "+f"(c3)
        : "r"(a0), "r"(a1), "r"(a2), "r"(a3), "r"(b0), "r"(b1));
}

__device__ __forceinline__ void cp16(float* dst_smem, const float* src) {
    unsigned s = (unsigned)__cvta_generic_to_shared(dst_smem);
    asm volatile("cp.async.cg.shared.global [%0], [%1], 16;" :: "r"(s), "l"(src) : "memory");
}

// ---------------- pre-pass: round weights to tf32 into g_wrnd ----------------
__global__ void __launch_bounds__(256) round_weights(
    const float* __restrict__ w0, const float* __restrict__ w1,
    const float* __restrict__ w2, const float* __restrict__ w3,
    const float* __restrict__ w4, const float* __restrict__ w5,
    const float* __restrict__ w6, const float* __restrict__ w7,
    float* __restrict__ wr)
{
    const float* src; int off; int len;
    switch (blockIdx.z) {
        case 0: src = w0; off = WO_M1INV; len = 131072; break;
        case 1: src = w1; off = WO_M1PW;  len = 65536;  break;
        case 2: src = w2; off = WO_KV;    len = 262144; break;
        case 3: src = w3; off = WO_QT;    len = 65536;  break;
        case 4: src = w4; off = WO_QRGB;  len = 65536;  break;
        case 5: src = w5; off = WO_PROJ;  len = 262144; break;
        case 6: src = w6; off = WO_M2INV; len = 262144; break;
        default: src = w7; off = WO_M2PW; len = 262144; break;
    }
    const int i = (blockIdx.x * 256 + threadIdx.x) * 4;
    if (i < len) {
        float4 v = *reinterpret_cast<const float4*>(src + i);
        v.x = rnd_tf32(v.x); v.y = rnd_tf32(v.y); v.z = rnd_tf32(v.z); v.w = rnd_tf32(v.w);
        *reinterpret_cast<float4*>(wr + off + i) = v;
    }
}

// ---------------- pre-pass: round rgb/t to tf32 copies ----------------
__global__ void __launch_bounds__(256) round_inputs(
    const float* __restrict__ rgb, const float* __restrict__ t,
    float* __restrict__ rgbr, float* __restrict__ tr)
{
    const float* src = blockIdx.z ? t : rgb;
    float* dst = blockIdx.z ? tr : rgbr;
    const int i = (blockIdx.x * 256 + threadIdx.x) * 4;
    float4 v = *reinterpret_cast<const float4*>(src + i);
    v.x = rnd_tf32(v.x); v.y = rnd_tf32(v.y); v.z = rnd_tf32(v.z); v.w = rnd_tf32(v.w);
    *reinterpret_cast<float4*>(dst + i) = v;
}

// ---------------- 1x1 conv as TF32 tensor-core GEMM, 3-stage cp.async ring ----------
// Inputs (W and X) must already be tf32-rounded; mainloop does plain LDS, no cvt.
#define NSTG 3
#define WSTG 4096            // words per W stage (128*32)
#define XSTR 136
#define XSTG (32 * XSTR)     // words per X stage (4352)
template <int ACT, int ROUND>
__global__ void __launch_bounds__(256, 2) gemm1x1(
    const float* __restrict__ inA, const float* __restrict__ inB,
    int CA, int CB,
    const float* __restrict__ W,
    const float* __restrict__ gamma, const float* __restrict__ beta,
    float* __restrict__ out, int Cout)
{
    extern __shared__ __align__(16) float dsm[];
    float* Wsm = dsm;                    // [NSTG][WSTG]
    float* Xsm = dsm + NSTG * WSTG;      // [NSTG][XSTG]

    const int b   = blockIdx.z;
    const int p0  = blockIdx.x * 128;
    const int m0  = blockIdx.y * 128;
    const int Cin = CA + CB;
    const int tid = threadIdx.x;
    const int lane = tid & 31;
    const int warp = tid >> 5;
    const int wm = (warp >> 2) * 64;
    const int wn = (warp & 3) * 32;
    const int l4  = lane & 3;
    const int l28 = lane >> 2;

    const int sWm  = tid >> 1;
    const int sWc0 = (tid & 1) * 4;
    const float* wrow = W + (size_t)(m0 + sWm) * Cin;
    const int sXk  = tid >> 3;
    const int sXj0 = (tid & 7) * 4;

    float acc[4][4][4];
#pragma unroll
    for (int i = 0; i < 4; i++)
#pragma unroll
        for (int j = 0; j < 4; j++)
#pragma unroll
            for (int r = 0; r < 4; r++) acc[i][j][r] = 0.0f;

    auto issueTile = [&](int s, int k0) {
        float* wbase = Wsm + s * WSTG;
#pragma unroll
        for (int q = 0; q < 4; q++) {
            const int c = sWc0 + q;
            cp16(&wbase[sWm * 32 + ((c ^ (sWm & 7)) << 2)], wrow + k0 + c * 4);
        }
        const int ci = k0 + sXk;
        const float* xs = (ci < CA) ? inA + ((size_t)b * CA + ci) * HW
                                    : inB + ((size_t)b * CB + (ci - CA)) * HW;
        float* xbase = Xsm + s * XSTG + sXk * XSTR;
#pragma unroll
        for (int q = 0; q < 4; q++) {
            const int j = sXj0 + q;
            cp16(&xbase[j * 4], xs + p0 + j * 4);
        }
        asm volatile("cp.async.commit_group;" ::: "memory");
    };

    auto compute = [&](int s) {
        const unsigned* Ws = reinterpret_cast<const unsigned*>(Wsm + s * WSTG);
        const unsigned* Xs = reinterpret_cast<const unsigned*>(Xsm + s * XSTG);
#pragma unroll
        for (int kb = 0; kb < 4; kb++) {
            const int xc0 = ((2 * kb) ^ l28) << 2;
            const int xc1 = ((2 * kb + 1) ^ l28) << 2;
            unsigned af[4][4];
            unsigned bf[4][2];
#pragma unroll
            for (int mt = 0; mt < 4; mt++) {
                const int ma = wm + mt * 16 + l28;
                af[mt][0] = Ws[ma * 32 + xc0 + l4];
                af[mt][1] = Ws[(ma + 8) * 32 + xc0 + l4];
                af[mt][2] = Ws[ma * 32 + xc1 + l4];
                af[mt][3] = Ws[(ma + 8) * 32 + xc1 + l4];
            }
#pragma unroll
            for (int nt = 0; nt < 4; nt++) {
                const int nb = wn + nt * 8 + l28;
                bf[nt][0] = Xs[(kb * 8 + l4) * XSTR + nb];
                bf[nt][1] = Xs[(kb * 8 + l4 + 4) * XSTR + nb];
            }
#pragma unroll
            for (int mt = 0; mt < 4; mt++)
#pragma unroll
                for (int nt = 0; nt < 4; nt++)
                    mma_tf32(acc[mt][nt][0], acc[mt][nt][1], acc[mt][nt][2], acc[mt][nt][3],
                             af[mt][0], af[mt][1], af[mt][2], af[mt][3],
                             bf[nt][0], bf[nt][1]);
        }
    };

    const int T = Cin >> 5;
    issueTile(0, 0);
    if (T > 1) issueTile(1, 32);
    int slot = 0;
    for (int t = 0; t < T; t++) {
        if (t + 1 < T) {
            asm volatile("cp.async.wait_group 1;" ::: "memory");
        } else {
            asm volatile("cp.async.wait_group 0;" ::: "memory");
        }
        __syncthreads();
        if (t + 2 < T) {
            int ns = slot + 2; if (ns >= NSTG) ns -= NSTG;
            issueTile(ns, (t + 2) << 5);
        }
        compute(slot);
        if (++slot == NSTG) slot = 0;
    }

    // epilogue
#pragma unroll
    for (int mt = 0; mt < 4; mt++) {
#pragma unroll
        for (int rr = 0; rr < 2; rr++) {
            const int co = m0 + wm + mt * 16 + l28 + rr * 8;
            const float g  = gamma ? gamma[co] : 1.0f;
            const float be = beta  ? beta[co]  : 0.0f;
            float* orow = out + ((size_t)b * Cout + co) * HW + p0 + wn + l4 * 2;
#pragma unroll
            for (int nt = 0; nt < 4; nt++) {
                float v0 = acc[mt][nt][rr * 2 + 0] * g + be;
                float v1 = acc[mt][nt][rr * 2 + 1] * g + be;
                if (ACT == 1) { v0 = hswish_f(v0); v1 = hswish_f(v1); }
                if (ROUND == 1) { v0 = rnd_tf32(v0); v1 = rnd_tf32(v1); }
                *reinterpret_cast<float2*>(&orow[nt * 8]) = make_float2(v0, v1);
            }
        }
    }
}

// ---------------- grouped 1x1 conv: per-group 32x32 GEMM, 128-pixel tiles ----------------
__global__ void __launch_bounds__(256) grouped_pw(
    const float* __restrict__ in, const float* __restrict__ W,
    float* __restrict__ out, int C)
{
    __shared__ __align__(16) float Wg[32][32];
    __shared__ __align__(16) float Xs[32][128];

    const int b  = blockIdx.z;
    const int g  = blockIdx.y;
    const int p0 = blockIdx.x * 128;
    const int tid = threadIdx.x;

    {
        const int co = tid >> 3;
        const int k  = (tid & 7) << 2;
        float4 w = *reinterpret_cast<const float4*>(&W[(size_t)(g * 32 + co) * 32 + k]);
        Wg[k + 0][co] = w.x; Wg[k + 1][co] = w.y; Wg[k + 2][co] = w.z; Wg[k + 3][co] = w.w;
    }
    {
        const int r = tid >> 5;
        const int c = (tid & 31) << 2;
#pragma unroll
        for (int rr = r; rr < 32; rr += 8) {
            *reinterpret_cast<float4*>(&Xs[rr][c]) =
                *reinterpret_cast<const float4*>(&in[((size_t)b * C + g * 32 + rr) * HW + p0 + c]);
        }
    }
    __syncthreads();

    const int ty = tid >> 5;
    const int tx = tid & 31;
    float acc[4][4];
#pragma unroll
    for (int i = 0; i < 4; i++)
#pragma unroll
        for (int j = 0; j < 4; j++) acc[i][j] = 0.0f;

#pragma unroll
    for (int k = 0; k < 32; k++) {
        float4 a = *reinterpret_cast<const float4*>(&Wg[k][ty * 4]);
        float4 x = *reinterpret_cast<const float4*>(&Xs[k][tx * 4]);
        float av[4] = {a.x, a.y, a.z, a.w};
        float xv[4] = {x.x, x.y, x.z, x.w};
#pragma unroll
        for (int i = 0; i < 4; i++)
#pragma unroll
            for (int j = 0; j < 4; j++)
                acc[i][j] += av[i] * xv[j];
    }

#pragma unroll
    for (int i = 0; i < 4; i++) {
        float* o = out + ((size_t)b * C + g * 32 + ty * 4 + i) * HW + p0 + tx * 4;
        *reinterpret_cast<float4*>(o) = make_float4(acc[i][0], acc[i][1], acc[i][2], acc[i][3]);
    }
}

// ---------------- depthwise KxK conv, full 64x64 image per block, float4 I/O ----------
template <int KS, int ACT, int ROUND>
__global__ void __launch_bounds__(256) dwconv(
    const float* __restrict__ in, const float* __restrict__ w,
    const float* __restrict__ gamma, const float* __restrict__ beta,
    float* __restrict__ out, int C)
{
    const int R = KS / 2;
    __shared__ __align__(16) float tile[68][72];   // data at rows R.., cols 4..
    __shared__ float wsm[25];

    const int ch = blockIdx.x;
    const int b  = blockIdx.y;
    const int tid = threadIdx.x;

    if (tid < KS * KS) wsm[tid] = w[(size_t)ch * KS * KS + tid];

    const int ROWS = 64 + 2 * R;
    for (int idx = tid; idx < ROWS * 18; idx += 256)
        *reinterpret_cast<float4*>(&tile[idx / 18][(idx % 18) * 4]) = make_float4(0.f, 0.f, 0.f, 0.f);
    __syncthreads();

    const float* src = in + ((size_t)b * C + ch) * HW;
#pragma unroll
    for (int i = 0; i < 4; i++) {
        const int idx = tid + i * 256;
        const int y  = idx >> 4;
        const int xq = (idx & 15) << 2;
        *reinterpret_cast<float4*>(&tile[y + R][4 + xq]) =
            *reinterpret_cast<const float4*>(&src[y * 64 + xq]);
    }
    __syncthreads();

    const float g  = gamma ? gamma[ch] : 1.0f;
    const float be = beta  ? beta[ch]  : 0.0f;
    const int oy0 = (tid >> 4) << 2;
    const int ox  = (tid & 15) << 2;
    float* dst = out + ((size_t)b * C + ch) * HW;

#pragma unroll
    for (int ry = 0; ry < 4; ry++) {
        const int oy = oy0 + ry;
        float o[4] = {0.f, 0.f, 0.f, 0.f};
#pragma unroll
        for (int dy = 0; dy < KS; dy++)
#pragma unroll
            for (int dx = 0; dx < KS; dx++) {
                const float wv = wsm[dy * KS + dx];
                const int colb = 4 - R + ox + dx;
#pragma unroll
                for (int j = 0; j < 4; j++)
                    o[j] += wv * tile[oy + dy][colb + j];
            }
        float v[4];
#pragma unroll
        for (int j = 0; j < 4; j++) {
            float r = o[j] * g + be;
            if (ACT == 1) r = hswish_f(r);
            if (ROUND == 1) r = rnd_tf32(r);
            v[j] = r;
        }
        *reinterpret_cast<float4*>(&dst[oy * 64 + ox]) = make_float4(v[0], v[1], v[2], v[3]);
    }
}

// ---------------- attention phase 1 (N-split partials, NCH=8) ----------
__global__ void __launch_bounds__(256) att_ctx(
    const float* __restrict__ kv, const float* __restrict__ kvs,
    float* __restrict__ ctxp)
{
    const int h = blockIdx.x;
    const int b = blockIdx.y;
    const int z = blockIdx.z;          // a*NCH + chunk
    const int a = z >> 3;
    const int chunk = z & (NCH - 1);
    const int hb = h & 7;
    const float* base  = (h < 8) ? kv : kvs;
    const float* kbase = base + ((size_t)b * 1024 + a * 512 + hb * 64) * HW;
    const float* vbase = kbase + (size_t)32 * HW;

    __shared__ __align__(16) float Ksm[128][33];
    __shared__ __align__(16) float Vsm[128][33];

    const int tid = threadIdx.x;
    const int d  = tid & 31;
    const int gq = tid >> 5;

    float acc0 = 0.f, acc1 = 0.f, acc2 = 0.f, acc3 = 0.f, acc4 = 0.f;

    const int nlo = chunk * (HW / NCH);
    const int nhi = nlo + (HW / NCH);
    for (int n0 = nlo; n0 < nhi; n0 += 128) {
        __syncthreads();
#pragma unroll
        for (int i = 0; i < 4; i++) {
            const int idx = tid + i * 256;
            const int ch = idx >> 5;
            const int nq = (idx & 31) << 2;
            float4 kx = *reinterpret_cast<const float4*>(&kbase[(size_t)ch * HW + n0 + nq]);
            float4 vx = *reinterpret_cast<const float4*>(&vbase[(size_t)ch * HW + n0 + nq]);
            Ksm[nq + 0][ch] = fmaxf(kx.x, 0.f);
            Ksm[nq + 1][ch] = fmaxf(kx.y, 0.f);
            Ksm[nq + 2][ch] = fmaxf(kx.z, 0.f);
            Ksm[nq + 3][ch] = fmaxf(kx.w, 0.f);
            Vsm[nq + 0][ch] = vx.x;
            Vsm[nq + 1][ch] = vx.y;
            Vsm[nq + 2][ch] = vx.z;
            Vsm[nq + 3][ch] = vx.w;
        }
        __syncthreads();
#pragma unroll 4
        for (int nn = 0; nn < 128; nn++) {
            const float kd = Ksm[nn][d];
            acc0 += kd * Vsm[nn][gq];
            acc1 += kd * Vsm[nn][gq + 8];
            acc2 += kd * Vsm[nn][gq + 16];
            acc3 += kd * Vsm[nn][gq + 24];
            if (gq == 0) acc4 += kd;
        }
    }

    float* cbase = ctxp + ((((size_t)z * NB + b) * 16 + h) * 32 + d) * 33;
    cbase[gq]      = acc0;
    cbase[gq + 8]  = acc1;
    cbase[gq + 16] = acc2;
    cbase[gq + 24] = acc3;
    if (gq == 0) cbase[32] = acc4;
}

// ---------------- attention phase 2 (sums NCH ctx partials; tf32-rounded output) --------
__global__ void __launch_bounds__(128) att_out(
    const float* __restrict__ qt, const float* __restrict__ qts,
    const float* __restrict__ qrgb, const float* __restrict__ qrgbs,
    const float* __restrict__ ctxp, float* __restrict__ out)
{
    const int n0 = blockIdx.x * 128;
    const int h  = blockIdx.y;
    const int a  = blockIdx.z >> 2;
    const int b  = blockIdx.z & 3;
    const int hb = h & 7;

    const float* q = (a == 0) ? ((h < 8) ? qt : qts) : ((h < 8) ? qrgb : qrgbs);
    q += ((size_t)b * 256 + hb * 32) * HW;

    __shared__ __align__(16) float Qsm[128][33];
    __shared__ __align__(16) float Csm[32 * 33];
    __shared__ __align__(16) float Osm[32][132];   // 132-stride: 16B-divisible rows

    const int tid = threadIdx.x;
#pragma unroll
    for (int i = 0; i < 8; i++) {
        const int idx = tid + i * 128;
        const int ch = idx >> 5;
        const int nq = (idx & 31) << 2;
        float4 x = *reinterpret_cast<const float4*>(&q[(size_t)ch * HW + n0 + nq]);
        Qsm[nq + 0][ch] = fmaxf(x.x, 0.f);
        Qsm[nq + 1][ch] = fmaxf(x.y, 0.f);
        Qsm[nq + 2][ch] = fmaxf(x.z, 0.f);
        Qsm[nq + 3][ch] = fmaxf(x.w, 0.f);
    }
    {
        for (int idx = tid; idx < 32 * 33; idx += 128) {
            float s = 0.0f;
#pragma unroll
            for (int c = 0; c < NCH; c++) {
                const float* cb = ctxp + ((((size_t)(a * NCH + c) * NB + b) * 16 + h) * 32) * 33;
                s += cb[idx];
            }
            Csm[idx] = s;
        }
    }
    __syncthreads();

    float acc[33];
#pragma unroll
    for (int e = 0; e < 33; e++) acc[e] = 0.0f;

#pragma unroll 4
    for (int dd = 0; dd < 32; dd++) {
        const float qd = Qsm[tid][dd];
#pragma unroll
        for (int e = 0; e < 33; e++)
            acc[e] += qd * Csm[dd * 33 + e];
    }
    const float inv = 1.0f / (acc[32] + EPS_ATT);
#pragma unroll
    for (int dd = 0; dd < 32; dd++) Osm[dd][tid] = rnd_tf32(acc[dd] * inv);
    __syncthreads();

    float* ob = out + ((size_t)b * 1024 + a * 512 + h * 32) * HW + n0;
#pragma unroll
    for (int i = 0; i < 8; i++) {
        const int idx = tid + i * 128;
        const int dd = idx >> 5;
        const int nq = (idx & 31) << 2;
        *reinterpret_cast<float4*>(&ob[(size_t)dd * HW + nq]) =
            *reinterpret_cast<const float4*>(&Osm[dd][nq]);
    }
}

// ---------------------------------- launcher ----------------------------------
extern "C" void kernel_launch(void* const* d_in, const int* in_sizes, int n_in,
                              void* d_out, int out_size)
{
    const float* rgb        = (const float*)d_in[0];
    const float* t_in       = (const float*)d_in[1];
    const float* m1_inv_w   = (const float*)d_in[2];
    const float* m1_inv_g   = (const float*)d_in[3];
    const float* m1_inv_b   = (const float*)d_in[4];
    const float* m1_dw_w    = (const float*)d_in[5];
    const float* m1_dw_g    = (const float*)d_in[6];
    const float* m1_dw_b    = (const float*)d_in[7];
    const float* m1_pw_w    = (const float*)d_in[8];
    const float* m1_pw_g    = (const float*)d_in[9];
    const float* m1_pw_b    = (const float*)d_in[10];
    const float* kv_w       = (const float*)d_in[11];
    const float* qrgb_w     = (const float*)d_in[12];
    const float* qt_w       = (const float*)d_in[13];
    const float* agg_kv_dw  = (const float*)d_in[14];
    const float* agg_kv_pw  = (const float*)d_in[15];
    const float* agg_t_dw   = (const float*)d_in[16];
    const float* agg_t_pw   = (const float*)d_in[17];
    const float* agg_rgb_dw = (const float*)d_in[18];
    const float* agg_rgb_pw = (const float*)d_in[19];
    const float* proj_w     = (const float*)d_in[20];
    const float* m2_inv_w   = (const float*)d_in[21];
    const float* m2_inv_bias= (const float*)d_in[22];
    const float* m2_dw_w    = (const float*)d_in[23];
    const float* m2_dw_bias = (const float*)d_in[24];
    const float* m2_pw_w    = (const float*)d_in[25];
    const float* m2_pw_g    = (const float*)d_in[26];
    const float* m2_pw_b    = (const float*)d_in[27];

    void* p;
    cudaGetSymbolAddress(&p, g_bufA);  float* bufA  = (float*)p;
    cudaGetSymbolAddress(&p, g_bufB);  float* bufB  = (float*)p;
    cudaGetSymbolAddress(&p, g_qt);    float* qtb   = (float*)p;
    cudaGetSymbolAddress(&p, g_qrgb);  float* qrgbb = (float*)p;
    cudaGetSymbolAddress(&p, g_qts);   float* qtsb  = (float*)p;
    cudaGetSymbolAddress(&p, g_qrgbs); float* qrgbsb= (float*)p;
    cudaGetSymbolAddress(&p, g_qtmp1); float* qtmp1 = (float*)p;
    cudaGetSymbolAddress(&p, g_qtmp2); float* qtmp2 = (float*)p;
    cudaGetSymbolAddress(&p, g_kv);    float* kvb   = (float*)p;
    cudaGetSymbolAddress(&p, g_kvtmp); float* kvtmp = (float*)p;
    cudaGetSymbolAddress(&p, g_kvs);   float* kvsb  = (float*)p;
    cudaGetSymbolAddress(&p, g_att);   float* attb  = (float*)p;
    cudaGetSymbolAddress(&p, g_ctxp);  float* ctxpb = (float*)p;
    cudaGetSymbolAddress(&p, g_wrnd);  float* wr    = (float*)p;
    cudaGetSymbolAddress(&p, g_rgbr);  float* rgbr  = (float*)p;
    cudaGetSymbolAddress(&p, g_tr);    float* tr    = (float*)p;

    const int SMEM = NSTG * (WSTG + XSTG) * 4;   // 101376 B
    cudaFuncSetAttribute(gemm1x1<0,0>, cudaFuncAttributeMaxDynamicSharedMemorySize, SMEM);
    cudaFuncSetAttribute(gemm1x1<0,1>, cudaFuncAttributeMaxDynamicSharedMemorySize, SMEM);
    cudaFuncSetAttribute(gemm1x1<1,0>, cudaFuncAttributeMaxDynamicSharedMemorySize, SMEM);
    cudaFuncSetAttribute(gemm1x1<1,1>, cudaFuncAttributeMaxDynamicSharedMemorySize, SMEM);

    // side stream + fork/join events (host resources, created once)
    static cudaStream_t s1 = nullptr;
    static cudaEvent_t evFork = nullptr, evJoin = nullptr;
    if (s1 == nullptr) {
        cudaStreamCreateWithFlags(&s1, cudaStreamNonBlocking);
        cudaEventCreateWithFlags(&evFork, cudaEventDisableTiming);
        cudaEventCreateWithFlags(&evJoin, cudaEventDisableTiming);
    }

    // pre-round weights + inputs to tf32
    round_weights<<<dim3(256, 1, 8), 256>>>(m1_inv_w, m1_pw_w, kv_w, qt_w, qrgb_w,
                                            proj_w, m2_inv_w, m2_pw_w, wr);
    round_inputs<<<dim3(4096, 1, 2), 256>>>(rgb, t_in, rgbr, tr);

    const dim3 g256(32, 2, NB);     // Cout=256
    const dim3 g1024(32, 8, NB);    // Cout=1024

    // ---- fork: q-path (independent of m1/kv chain) runs on s1 ----
    cudaEventRecord(evFork, 0);
    cudaStreamWaitEvent(s1, evFork, 0);

    gemm1x1<0,0><<<g256, 256, SMEM, s1>>>(tr, nullptr, 256, 0, wr + WO_QT, nullptr, nullptr, qtb, 256);
    gemm1x1<0,0><<<g256, 256, SMEM, s1>>>(rgbr, nullptr, 256, 0, wr + WO_QRGB, nullptr, nullptr, qrgbb, 256);
    dwconv<5, 0, 0><<<dim3(256, NB), 256, 0, s1>>>(qtb, agg_t_dw, nullptr, nullptr, qtmp1, 256);
    grouped_pw<<<dim3(32, 8, NB), 256, 0, s1>>>(qtmp1, agg_t_pw, qtsb, 256);
    dwconv<5, 0, 0><<<dim3(256, NB), 256, 0, s1>>>(qrgbb, agg_rgb_dw, nullptr, nullptr, qtmp2, 256);
    grouped_pw<<<dim3(32, 8, NB), 256, 0, s1>>>(qtmp2, agg_rgb_pw, qrgbsb, 256);
    cudaEventRecord(evJoin, s1);

    // ---- main chain: m1 bottleneck -> kv -> aggregation -> att_ctx ----
    gemm1x1<1,0><<<g256, 256, SMEM>>>(rgbr, tr, 256, 256, wr + WO_M1INV, m1_inv_g, m1_inv_b, bufA, 256);
    dwconv<3, 1, 1><<<dim3(256, NB), 256>>>(bufA, m1_dw_w, m1_dw_g, m1_dw_b, bufB, 256);
    gemm1x1<0,1><<<g256, 256, SMEM>>>(bufB, nullptr, 256, 0, wr + WO_M1PW, m1_pw_g, m1_pw_b, bufA, 256);
    gemm1x1<0,0><<<g1024, 256, SMEM>>>(bufA, nullptr, 256, 0, wr + WO_KV, nullptr, nullptr, kvb, 1024);
    dwconv<5, 0, 0><<<dim3(1024, NB), 256>>>(kvb, agg_kv_dw, nullptr, nullptr, kvtmp, 1024);
    grouped_pw<<<dim3(32, 32, NB), 256>>>(kvtmp, agg_kv_pw, kvsb, 1024);
    att_ctx<<<dim3(16, NB, 2 * NCH), 256>>>(kvb, kvsb, ctxpb);

    // ---- join, then attention output + m2 chain ----
    cudaStreamWaitEvent(0, evJoin, 0);
    att_out<<<dim3(32, 16, 2 * NB), 128>>>(qtb, qtsb, qrgbb, qrgbsb, ctxpb, attb);

    gemm1x1<0,1><<<g256, 256, SMEM>>>(attb, nullptr, 1024, 0, wr + WO_PROJ, nullptr, nullptr, bufA, 256);
    gemm1x1<1,0><<<g1024, 256, SMEM>>>(bufA, nullptr, 256, 0, wr + WO_M2INV, nullptr, m2_inv_bias, kvtmp, 1024);
    dwconv<3, 1, 1><<<dim3(1024, NB), 256>>>(kvtmp, m2_dw_w, nullptr, m2_dw_bias, kvsb, 1024);
    gemm1x1<0,0><<<g256, 256, SMEM>>>(kvsb, nullptr, 1024, 0, wr + WO_M2PW, m2_pw_g, m2_pw_b, (float*)d_out, 256);
}

// round 13
// speedup vs baseline: 1.2239x; 1.0333x over previous
#include <cuda_runtime.h>
#include <cstddef>

#define HW 4096
#define NB 4
#define EPS_ATT 1e-15f
#define NCH 8   // att_ctx N-split chunks

// ---------------- scratch (device globals; no allocation allowed) ----------------
__device__ __align__(16) float g_bufA[NB * 256 * HW];
__device__ __align__(16) float g_bufB[NB * 256 * HW];
__device__ __align__(16) float g_qt[NB * 256 * HW];
__device__ __align__(16) float g_qrgb[NB * 256 * HW];
__device__ __align__(16) float g_qts[NB * 256 * HW];
__device__ __align__(16) float g_qrgbs[NB * 256 * HW];
__device__ __align__(16) float g_qtmp1[NB * 256 * HW];
__device__ __align__(16) float g_qtmp2[NB * 256 * HW];
__device__ __align__(16) float g_kv[NB * 1024 * HW];
__device__ __align__(16) float g_kvtmp[NB * 1024 * HW];
__device__ __align__(16) float g_kvs[NB * 1024 * HW];
__device__ __align__(16) float g_att[NB * 1024 * HW];
__device__ __align__(16) float g_ctxp[2 * NCH * NB * 16 * 32 * 33];
// tf32-rounded copies (weights: fragment-major tiled layout)
__device__ __align__(16) float g_wrnd[1376256];
__device__ __align__(16) float g_rgbr[NB * 256 * HW];
__device__ __align__(16) float g_tr[NB * 256 * HW];

// rounded-weight offsets (floats)
#define WO_M1INV 0
#define WO_M1PW  131072
#define WO_KV    196608
#define WO_QT    458752
#define WO_QRGB  524288
#define WO_PROJ  589824
#define WO_M2INV 851968
#define WO_M2PW  1114112

__device__ __forceinline__ float hswish_f(float x) {
    return x * fminf(fmaxf(x + 3.0f, 0.0f), 6.0f) * (1.0f / 6.0f);
}

__device__ __forceinline__ unsigned f2tf32(float x) {
    unsigned r;
    asm("cvt.rna.tf32.f32 %0, %1;" : "=r"(r) : "f"(x));
    return r;
}
__device__ __forceinline__ float rnd_tf32(float x) {
    return __uint_as_float(f2tf32(x));
}

__device__ __forceinline__ void mma_tf32(
    float& c0, float& c1, float& c2, float& c3,
    unsigned a0, unsigned a1, unsigned a2, unsigned a3,
    unsigned b0, unsigned b1)
{
    asm volatile(
        "mma.sync.aligned.m16n8k8.row.col.f32.tf32.tf32.f32 "
        "{%0,%1,%2,%3}, {%4,%5,%6,%7}, {%8,%9}, {%0,%1,%2,%3};"
        : "+f"(c0), "+f"(c1), "+f"(c2), "+f"(c3)
        : "r"(a0), "r"(a1), "r"(a2), "r"(a3), "r"(b0), "r"(b1));
}

__device__ __forceinline__ void cp16(float* dst_smem, const float* src) {
    unsigned s = (unsigned)__cvta_generic_to_shared(dst_smem);
    asm volatile("cp.async.cg.shared.global [%0], [%1], 16;" :: "r"(s), "l"(src) : "memory");
}

// ---------------- pre-pass: round + fragment-major tile weights into g_wrnd ----------
// Per (128-row m-block, 32-col k-tile): 4096-word block. Each mma lane's A
// fragment is one contiguous uint4 at word ((kb*8 + mtile)*32 + lane)*4, with
// components (a0,a1,a2,a3) = (half0,kh0),(half1,kh0),(half0,kh1),(half1,kh1).
// lane = (m&7)*4 + (k&3).
__global__ void __launch_bounds__(256) round_weights(
    const float* __restrict__ w0, const float* __restrict__ w1,
    const float* __restrict__ w2, const float* __restrict__ w3,
    const float* __restrict__ w4, const float* __restrict__ w5,
    const float* __restrict__ w6, const float* __restrict__ w7,
    float* __restrict__ wr)
{
    const float* src; int off; int Cin; int len;
    switch (blockIdx.z) {
        case 0: src = w0; off = WO_M1INV; Cin = 512;  len = 131072; break;
        case 1: src = w1; off = WO_M1PW;  Cin = 256;  len = 65536;  break;
        case 2: src = w2; off = WO_KV;    Cin = 256;  len = 262144; break;
        case 3: src = w3; off = WO_QT;    Cin = 256;  len = 65536;  break;
        case 4: src = w4; off = WO_QRGB;  Cin = 256;  len = 65536;  break;
        case 5: src = w5; off = WO_PROJ;  Cin = 1024; len = 262144; break;
        case 6: src = w6; off = WO_M2INV; Cin = 256;  len = 262144; break;
        default: src = w7; off = WO_M2PW; Cin = 1024; len = 262144; break;
    }
    const int i = (blockIdx.x * 256 + threadIdx.x) * 4;   // k..k+3 same kb/khalf
    if (i < len) {
        float4 v = *reinterpret_cast<const float4*>(src + i);
        const float u[4] = {rnd_tf32(v.x), rnd_tf32(v.y), rnd_tf32(v.z), rnd_tf32(v.w)};
        const int m = i / Cin;
        const int k = i - m * Cin;
        const int blk   = (m >> 7) * (Cin >> 5) + (k >> 5);
        const int mtile = (m >> 4) & 7;
        const int half  = (m >> 3) & 1;
        const int ml    = m & 7;
        const int kb    = (k >> 3) & 3;
        const int khalf = (k >> 2) & 1;
        const int base  = off + blk * 4096
                        + ((kb * 8 + mtile) * 32 + ml * 4) * 4 + khalf * 2 + half;
#pragma unroll
        for (int j = 0; j < 4; j++)
            wr[base + j * 4] = u[j];    // j = k&3 -> +1 lane = +4 words
    }
}

// ---------------- pre-pass: round rgb/t to tf32 copies ----------------
__global__ void __launch_bounds__(256) round_inputs(
    const float* __restrict__ rgb, const float* __restrict__ t,
    float* __restrict__ rgbr, float* __restrict__ tr)
{
    const float* src = blockIdx.z ? t : rgb;
    float* dst = blockIdx.z ? tr : rgbr;
    const int i = (blockIdx.x * 256 + threadIdx.x) * 4;
    float4 v = *reinterpret_cast<const float4*>(src + i);
    v.x = rnd_tf32(v.x); v.y = rnd_tf32(v.y); v.z = rnd_tf32(v.z); v.w = rnd_tf32(v.w);
    *reinterpret_cast<float4*>(dst + i) = v;
}

// ---------------- 1x1 conv as TF32 tensor-core GEMM, 3-stage cp.async ring ----------
// W: fragment-major tiled layout (see round_weights) -> linear staging + LDS.128 frags.
// X: [k][n] rows, stride 136 -> conflict-free scalar B-frag LDS.
#define NSTG 3
#define WSTG 4096            // words per W stage
#define XSTR 136
#define XSTG (32 * XSTR)     // words per X stage (4352)
template <int ACT, int ROUND>
__global__ void __launch_bounds__(256, 2) gemm1x1(
    const float* __restrict__ inA, const float* __restrict__ inB,
    int CA, int CB,
    const float* __restrict__ W,      // tiled fragment-major base (wr + off)
    const float* __restrict__ gamma, const float* __restrict__ beta,
    float* __restrict__ out, int Cout)
{
    extern __shared__ __align__(16) float dsm[];
    float* Wsm = dsm;                    // [NSTG][WSTG]
    float* Xsm = dsm + NSTG * WSTG;      // [NSTG][XSTG]

    const int b   = blockIdx.z;
    const int p0  = blockIdx.x * 128;
    const int m0  = blockIdx.y * 128;
    const int Cin = CA + CB;
    const int Ktiles = Cin >> 5;
    const int tid = threadIdx.x;
    const int lane = tid & 31;
    const int warp = tid >> 5;
    const int wm = (warp >> 2) * 64;
    const int wn = (warp & 3) * 32;
    const int mt0 = (warp >> 2) * 4;     // base mtile for this warp
    const int l4  = lane & 3;
    const int l28 = lane >> 2;

    const float* wtile = W + (size_t)(m0 >> 7) * Ktiles * 4096 + tid * 16;
    const int sXk  = tid >> 3;
    const int sXj0 = (tid & 7) * 4;

    float acc[4][4][4];
#pragma unroll
    for (int i = 0; i < 4; i++)
#pragma unroll
        for (int j = 0; j < 4; j++)
#pragma unroll
            for (int r = 0; r < 4; r++) acc[i][j][r] = 0.0f;

    auto issueTile = [&](int s, int t) {
        // W: fully linear 16KB block -> 4 cp16/thread
        float* wb = Wsm + s * WSTG + tid * 16;
        const float* ws = wtile + (size_t)t * 4096;
#pragma unroll
        for (int q = 0; q < 4; q++)
            cp16(wb + q * 4, ws + q * 4);
        // X: rows of 128 px
        const int k0 = t << 5;
        const int ci = k0 + sXk;
        const float* xs = (ci < CA) ? inA + ((size_t)b * CA + ci) * HW
                                    : inB + ((size_t)b * CB + (ci - CA)) * HW;
        float* xbase = Xsm + s * XSTG + sXk * XSTR;
#pragma unroll
        for (int q = 0; q < 4; q++) {
            const int j = sXj0 + q;
            cp16(&xbase[j * 4], xs + p0 + j * 4);
        }
        asm volatile("cp.async.commit_group;" ::: "memory");
    };

    auto compute = [&](int s) {
        const unsigned* Ws = reinterpret_cast<const unsigned*>(Wsm + s * WSTG);
        const unsigned* Xs = reinterpret_cast<const unsigned*>(Xsm + s * XSTG);
#pragma unroll
        for (int kb = 0; kb < 4; kb++) {
            unsigned af[4][4];
            unsigned bf[4][2];
#pragma unroll
            for (int mt = 0; mt < 4; mt++) {
                uint4 a = *reinterpret_cast<const uint4*>(
                    &Ws[((kb * 8 + mt0 + mt) * 32 + lane) * 4]);
                af[mt][0] = a.x; af[mt][1] = a.y; af[mt][2] = a.z; af[mt][3] = a.w;
            }
#pragma unroll
            for (int nt = 0; nt < 4; nt++) {
                const int nb = wn + nt * 8 + l28;
                bf[nt][0] = Xs[(kb * 8 + l4) * XSTR + nb];
                bf[nt][1] = Xs[(kb * 8 + l4 + 4) * XSTR + nb];
            }
#pragma unroll
            for (int mt = 0; mt < 4; mt++)
#pragma unroll
                for (int nt = 0; nt < 4; nt++)
                    mma_tf32(acc[mt][nt][0], acc[mt][nt][1], acc[mt][nt][2], acc[mt][nt][3],
                             af[mt][0], af[mt][1], af[mt][2], af[mt][3],
                             bf[nt][0], bf[nt][1]);
        }
    };

    const int T = Ktiles;
    issueTile(0, 0);
    if (T > 1) issueTile(1, 1);
    int slot = 0;
    for (int t = 0; t < T; t++) {
        if (t + 1 < T) {
            asm volatile("cp.async.wait_group 1;" ::: "memory");
        } else {
            asm volatile("cp.async.wait_group 0;" ::: "memory");
        }
        __syncthreads();
        if (t + 2 < T) {
            int ns = slot + 2; if (ns >= NSTG) ns -= NSTG;
            issueTile(ns, t + 2);
        }
        compute(slot);
        if (++slot == NSTG) slot = 0;
    }

    // epilogue
#pragma unroll
    for (int mt = 0; mt < 4; mt++) {
#pragma unroll
        for (int rr = 0; rr < 2; rr++) {
            const int co = m0 + wm + mt * 16 + l28 + rr * 8;
            const float g  = gamma ? gamma[co] : 1.0f;
            const float be = beta  ? beta[co]  : 0.0f;
            float* orow = out + ((size_t)b * Cout + co) * HW + p0 + wn + l4 * 2;
#pragma unroll
            for (int nt = 0; nt < 4; nt++) {
                float v0 = acc[mt][nt][rr * 2 + 0] * g + be;
                float v1 = acc[mt][nt][rr * 2 + 1] * g + be;
                if (ACT == 1) { v0 = hswish_f(v0); v1 = hswish_f(v1); }
                if (ROUND == 1) { v0 = rnd_tf32(v0); v1 = rnd_tf32(v1); }
                *reinterpret_cast<float2*>(&orow[nt * 8]) = make_float2(v0, v1);
            }
        }
    }
}

// ---------------- grouped 1x1 conv: per-group 32x32 GEMM, 128-pixel tiles ----------------
__global__ void __launch_bounds__(256) grouped_pw(
    const float* __restrict__ in, const float* __restrict__ W,
    float* __restrict__ out, int C)
{
    __shared__ __align__(16) float Wg[32][32];
    __shared__ __align__(16) float Xs[32][128];

    const int b  = blockIdx.z;
    const int g  = blockIdx.y;
    const int p0 = blockIdx.x * 128;
    const int tid = threadIdx.x;

    {
        const int co = tid >> 3;
        const int k  = (tid & 7) << 2;
        float4 w = *reinterpret_cast<const float4*>(&W[(size_t)(g * 32 + co) * 32 + k]);
        Wg[k + 0][co] = w.x; Wg[k + 1][co] = w.y; Wg[k + 2][co] = w.z; Wg[k + 3][co] = w.w;
    }
    {
        const int r = tid >> 5;
        const int c = (tid & 31) << 2;
#pragma unroll
        for (int rr = r; rr < 32; rr += 8) {
            *reinterpret_cast<float4*>(&Xs[rr][c]) =
                *reinterpret_cast<const float4*>(&in[((size_t)b * C + g * 32 + rr) * HW + p0 + c]);
        }
    }
    __syncthreads();

    const int ty = tid >> 5;
    const int tx = tid & 31;
    float acc[4][4];
#pragma unroll
    for (int i = 0; i < 4; i++)
#pragma unroll
        for (int j = 0; j < 4; j++) acc[i][j] = 0.0f;

#pragma unroll
    for (int k = 0; k < 32; k++) {
        float4 a = *reinterpret_cast<const float4*>(&Wg[k][ty * 4]);
        float4 x = *reinterpret_cast<const float4*>(&Xs[k][tx * 4]);
        float av[4] = {a.x, a.y, a.z, a.w};
        float xv[4] = {x.x, x.y, x.z, x.w};
#pragma unroll
        for (int i = 0; i < 4; i++)
#pragma unroll
            for (int j = 0; j < 4; j++)
                acc[i][j] += av[i] * xv[j];
    }

#pragma unroll
    for (int i = 0; i < 4; i++) {
        float* o = out + ((size_t)b * C + g * 32 + ty * 4 + i) * HW + p0 + tx * 4;
        *reinterpret_cast<float4*>(o) = make_float4(acc[i][0], acc[i][1], acc[i][2], acc[i][3]);
    }
}

// ---------------- depthwise KxK conv, full 64x64 image per block, float4 I/O ----------
template <int KS, int ACT, int ROUND>
__global__ void __launch_bounds__(256) dwconv(
    const float* __restrict__ in, const float* __restrict__ w,
    const float* __restrict__ gamma, const float* __restrict__ beta,
    float* __restrict__ out, int C)
{
    const int R = KS / 2;
    __shared__ __align__(16) float tile[68][72];   // data at rows R.., cols 4..
    __shared__ float wsm[25];

    const int ch = blockIdx.x;
    const int b  = blockIdx.y;
    const int tid = threadIdx.x;

    if (tid < KS * KS) wsm[tid] = w[(size_t)ch * KS * KS + tid];

    const int ROWS = 64 + 2 * R;
    for (int idx = tid; idx < ROWS * 18; idx += 256)
        *reinterpret_cast<float4*>(&tile[idx / 18][(idx % 18) * 4]) = make_float4(0.f, 0.f, 0.f, 0.f);
    __syncthreads();

    const float* src = in + ((size_t)b * C + ch) * HW;
#pragma unroll
    for (int i = 0; i < 4; i++) {
        const int idx = tid + i * 256;
        const int y  = idx >> 4;
        const int xq = (idx & 15) << 2;
        *reinterpret_cast<float4*>(&tile[y + R][4 + xq]) =
            *reinterpret_cast<const float4*>(&src[y * 64 + xq]);
    }
    __syncthreads();

    const float g  = gamma ? gamma[ch] : 1.0f;
    const float be = beta  ? beta[ch]  : 0.0f;
    const int oy0 = (tid >> 4) << 2;
    const int ox  = (tid & 15) << 2;
    float* dst = out + ((size_t)b * C + ch) * HW;

#pragma unroll
    for (int ry = 0; ry < 4; ry++) {
        const int oy = oy0 + ry;
        float o[4] = {0.f, 0.f, 0.f, 0.f};
#pragma unroll
        for (int dy = 0; dy < KS; dy++)
#pragma unroll
            for (int dx = 0; dx < KS; dx++) {
                const float wv = wsm[dy * KS + dx];
                const int colb = 4 - R + ox + dx;
#pragma unroll
                for (int j = 0; j < 4; j++)
                    o[j] += wv * tile[oy + dy][colb + j];
            }
        float v[4];
#pragma unroll
        for (int j = 0; j < 4; j++) {
            float r = o[j] * g + be;
            if (ACT == 1) r = hswish_f(r);
            if (ROUND == 1) r = rnd_tf32(r);
            v[j] = r;
        }
        *reinterpret_cast<float4*>(&dst[oy * 64 + ox]) = make_float4(v[0], v[1], v[2], v[3]);
    }
}

// ---------------- attention phase 1 (N-split partials, NCH=8) ----------
__global__ void __launch_bounds__(256) att_ctx(
    const float* __restrict__ kv, const float* __restrict__ kvs,
    float* __restrict__ ctxp)
{
    const int h = blockIdx.x;
    const int b = blockIdx.y;
    const int z = blockIdx.z;          // a*NCH + chunk
    const int a = z >> 3;
    const int chunk = z & (NCH - 1);
    const int hb = h & 7;
    const float* base  = (h < 8) ? kv : kvs;
    const float* kbase = base + ((size_t)b * 1024 + a * 512 + hb * 64) * HW;
    const float* vbase = kbase + (size_t)32 * HW;

    __shared__ __align__(16) float Ksm[128][33];
    __shared__ __align__(16) float Vsm[128][33];

    const int tid = threadIdx.x;
    const int d  = tid & 31;
    const int gq = tid >> 5;

    float acc0 = 0.f, acc1 = 0.f, acc2 = 0.f, acc3 = 0.f, acc4 = 0.f;

    const int nlo = chunk * (HW / NCH);
    const int nhi = nlo + (HW / NCH);
    for (int n0 = nlo; n0 < nhi; n0 += 128) {
        __syncthreads();
#pragma unroll
        for (int i = 0; i < 4; i++) {
            const int idx = tid + i * 256;
            const int ch = idx >> 5;
            const int nq = (idx & 31) << 2;
            float4 kx = *reinterpret_cast<const float4*>(&kbase[(size_t)ch * HW + n0 + nq]);
            float4 vx = *reinterpret_cast<const float4*>(&vbase[(size_t)ch * HW + n0 + nq]);
            Ksm[nq + 0][ch] = fmaxf(kx.x, 0.f);
            Ksm[nq + 1][ch] = fmaxf(kx.y, 0.f);
            Ksm[nq + 2][ch] = fmaxf(kx.z, 0.f);
            Ksm[nq + 3][ch] = fmaxf(kx.w, 0.f);
            Vsm[nq + 0][ch] = vx.x;
            Vsm[nq + 1][ch] = vx.y;
            Vsm[nq + 2][ch] = vx.z;
            Vsm[nq + 3][ch] = vx.w;
        }
        __syncthreads();
#pragma unroll 4
        for (int nn = 0; nn < 128; nn++) {
            const float kd = Ksm[nn][d];
            acc0 += kd * Vsm[nn][gq];
            acc1 += kd * Vsm[nn][gq + 8];
            acc2 += kd * Vsm[nn][gq + 16];
            acc3 += kd * Vsm[nn][gq + 24];
            if (gq == 0) acc4 += kd;
        }
    }

    float* cbase = ctxp + ((((size_t)z * NB + b) * 16 + h) * 32 + d) * 33;
    cbase[gq]      = acc0;
    cbase[gq + 8]  = acc1;
    cbase[gq + 16] = acc2;
    cbase[gq + 24] = acc3;
    if (gq == 0) cbase[32] = acc4;
}

// ---------------- attention phase 2 (sums NCH ctx partials; tf32-rounded output) --------
__global__ void __launch_bounds__(128) att_out(
    const float* __restrict__ qt, const float* __restrict__ qts,
    const float* __restrict__ qrgb, const float* __restrict__ qrgbs,
    const float* __restrict__ ctxp, float* __restrict__ out)
{
    const int n0 = blockIdx.x * 128;
    const int h  = blockIdx.y;
    const int a  = blockIdx.z >> 2;
    const int b  = blockIdx.z & 3;
    const int hb = h & 7;

    const float* q = (a == 0) ? ((h < 8) ? qt : qts) : ((h < 8) ? qrgb : qrgbs);
    q += ((size_t)b * 256 + hb * 32) * HW;

    __shared__ __align__(16) float Qsm[128][33];
    __shared__ __align__(16) float Csm[32 * 33];
    __shared__ __align__(16) float Osm[32][132];   // 132-stride: 16B-divisible rows

    const int tid = threadIdx.x;
#pragma unroll
    for (int i = 0; i < 8; i++) {
        const int idx = tid + i * 128;
        const int ch = idx >> 5;
        const int nq = (idx & 31) << 2;
        float4 x = *reinterpret_cast<const float4*>(&q[(size_t)ch * HW + n0 + nq]);
        Qsm[nq + 0][ch] = fmaxf(x.x, 0.f);
        Qsm[nq + 1][ch] = fmaxf(x.y, 0.f);
        Qsm[nq + 2][ch] = fmaxf(x.z, 0.f);
        Qsm[nq + 3][ch] = fmaxf(x.w, 0.f);
    }
    {
        for (int idx = tid; idx < 32 * 33; idx += 128) {
            float s = 0.0f;
#pragma unroll
            for (int c = 0; c < NCH; c++) {
                const float* cb = ctxp + ((((size_t)(a * NCH + c) * NB + b) * 16 + h) * 32) * 33;
                s += cb[idx];
            }
            Csm[idx] = s;
        }
    }
    __syncthreads();

    float acc[33];
#pragma unroll
    for (int e = 0; e < 33; e++) acc[e] = 0.0f;

#pragma unroll 4
    for (int dd = 0; dd < 32; dd++) {
        const float qd = Qsm[tid][dd];
#pragma unroll
        for (int e = 0; e < 33; e++)
            acc[e] += qd * Csm[dd * 33 + e];
    }
    const float inv = 1.0f / (acc[32] + EPS_ATT);
#pragma unroll
    for (int dd = 0; dd < 32; dd++) Osm[dd][tid] = rnd_tf32(acc[dd] * inv);
    __syncthreads();

    float* ob = out + ((size_t)b * 1024 + a * 512 + h * 32) * HW + n0;
#pragma unroll
    for (int i = 0; i < 8; i++) {
        const int idx = tid + i * 128;
        const int dd = idx >> 5;
        const int nq = (idx & 31) << 2;
        *reinterpret_cast<float4*>(&ob[(size_t)dd * HW + nq]) =
            *reinterpret_cast<const float4*>(&Osm[dd][nq]);
    }
}

// ---------------------------------- launcher ----------------------------------
extern "C" void kernel_launch(void* const* d_in, const int* in_sizes, int n_in,
                              void* d_out, int out_size)
{
    const float* rgb        = (const float*)d_in[0];
    const float* t_in       = (const float*)d_in[1];
    const float* m1_inv_w   = (const float*)d_in[2];
    const float* m1_inv_g   = (const float*)d_in[3];
    const float* m1_inv_b   = (const float*)d_in[4];
    const float* m1_dw_w    = (const float*)d_in[5];
    const float* m1_dw_g    = (const float*)d_in[6];
    const float* m1_dw_b    = (const float*)d_in[7];
    const float* m1_pw_w    = (const float*)d_in[8];
    const float* m1_pw_g    = (const float*)d_in[9];
    const float* m1_pw_b    = (const float*)d_in[10];
    const float* kv_w       = (const float*)d_in[11];
    const float* qrgb_w     = (const float*)d_in[12];
    const float* qt_w       = (const float*)d_in[13];
    const float* agg_kv_dw  = (const float*)d_in[14];
    const float* agg_kv_pw  = (const float*)d_in[15];
    const float* agg_t_dw   = (const float*)d_in[16];
    const float* agg_t_pw   = (const float*)d_in[17];
    const float* agg_rgb_dw = (const float*)d_in[18];
    const float* agg_rgb_pw = (const float*)d_in[19];
    const float* proj_w     = (const float*)d_in[20];
    const float* m2_inv_w   = (const float*)d_in[21];
    const float* m2_inv_bias= (const float*)d_in[22];
    const float* m2_dw_w    = (const float*)d_in[23];
    const float* m2_dw_bias = (const float*)d_in[24];
    const float* m2_pw_w    = (const float*)d_in[25];
    const float* m2_pw_g    = (const float*)d_in[26];
    const float* m2_pw_b    = (const float*)d_in[27];

    void* p;
    cudaGetSymbolAddress(&p, g_bufA);  float* bufA  = (float*)p;
    cudaGetSymbolAddress(&p, g_bufB);  float* bufB  = (float*)p;
    cudaGetSymbolAddress(&p, g_qt);    float* qtb   = (float*)p;
    cudaGetSymbolAddress(&p, g_qrgb);  float* qrgbb = (float*)p;
    cudaGetSymbolAddress(&p, g_qts);   float* qtsb  = (float*)p;
    cudaGetSymbolAddress(&p, g_qrgbs); float* qrgbsb= (float*)p;
    cudaGetSymbolAddress(&p, g_qtmp1); float* qtmp1 = (float*)p;
    cudaGetSymbolAddress(&p, g_qtmp2); float* qtmp2 = (float*)p;
    cudaGetSymbolAddress(&p, g_kv);    float* kvb   = (float*)p;
    cudaGetSymbolAddress(&p, g_kvtmp); float* kvtmp = (float*)p;
    cudaGetSymbolAddress(&p, g_kvs);   float* kvsb  = (float*)p;
    cudaGetSymbolAddress(&p, g_att);   float* attb  = (float*)p;
    cudaGetSymbolAddress(&p, g_ctxp);  float* ctxpb = (float*)p;
    cudaGetSymbolAddress(&p, g_wrnd);  float* wr    = (float*)p;
    cudaGetSymbolAddress(&p, g_rgbr);  float* rgbr  = (float*)p;
    cudaGetSymbolAddress(&p, g_tr);    float* tr    = (float*)p;

    const int SMEM = NSTG * (WSTG + XSTG) * 4;   // 101376 B
    cudaFuncSetAttribute(gemm1x1<0,0>, cudaFuncAttributeMaxDynamicSharedMemorySize, SMEM);
    cudaFuncSetAttribute(gemm1x1<0,1>, cudaFuncAttributeMaxDynamicSharedMemorySize, SMEM);
    cudaFuncSetAttribute(gemm1x1<1,0>, cudaFuncAttributeMaxDynamicSharedMemorySize, SMEM);
    cudaFuncSetAttribute(gemm1x1<1,1>, cudaFuncAttributeMaxDynamicSharedMemorySize, SMEM);

    // side stream + fork/join events (host resources, created once)
    static cudaStream_t s1 = nullptr;
    static cudaEvent_t evFork = nullptr, evJoin = nullptr;
    if (s1 == nullptr) {
        cudaStreamCreateWithFlags(&s1, cudaStreamNonBlocking);
        cudaEventCreateWithFlags(&evFork, cudaEventDisableTiming);
        cudaEventCreateWithFlags(&evJoin, cudaEventDisableTiming);
    }

    // pre-round weights (fragment-major tiled) + inputs to tf32
    round_weights<<<dim3(256, 1, 8), 256>>>(m1_inv_w, m1_pw_w, kv_w, qt_w, qrgb_w,
                                            proj_w, m2_inv_w, m2_pw_w, wr);
    round_inputs<<<dim3(4096, 1, 2), 256>>>(rgb, t_in, rgbr, tr);

    const dim3 g256(32, 2, NB);     // Cout=256
    const dim3 g1024(32, 8, NB);    // Cout=1024

    // ---- fork: q-path (independent of m1/kv chain) runs on s1 ----
    cudaEventRecord(evFork, 0);
    cudaStreamWaitEvent(s1, evFork, 0);

    gemm1x1<0,0><<<g256, 256, SMEM, s1>>>(tr, nullptr, 256, 0, wr + WO_QT, nullptr, nullptr, qtb, 256);
    gemm1x1<0,0><<<g256, 256, SMEM, s1>>>(rgbr, nullptr, 256, 0, wr + WO_QRGB, nullptr, nullptr, qrgbb, 256);
    dwconv<5, 0, 0><<<dim3(256, NB), 256, 0, s1>>>(qtb, agg_t_dw, nullptr, nullptr, qtmp1, 256);
    grouped_pw<<<dim3(32, 8, NB), 256, 0, s1>>>(qtmp1, agg_t_pw, qtsb, 256);
    dwconv<5, 0, 0><<<dim3(256, NB), 256, 0, s1>>>(qrgbb, agg_rgb_dw, nullptr, nullptr, qtmp2, 256);
    grouped_pw<<<dim3(32, 8, NB), 256, 0, s1>>>(qtmp2, agg_rgb_pw, qrgbsb, 256);
    cudaEventRecord(evJoin, s1);

    // ---- main chain: m1 bottleneck -> kv -> aggregation -> att_ctx ----
    gemm1x1<1,0><<<g256, 256, SMEM>>>(rgbr, tr, 256, 256, wr + WO_M1INV, m1_inv_g, m1_inv_b, bufA, 256);
    dwconv<3, 1, 1><<<dim3(256, NB), 256>>>(bufA, m1_dw_w, m1_dw_g, m1_dw_b, bufB, 256);
    gemm1x1<0,1><<<g256, 256, SMEM>>>(bufB, nullptr, 256, 0, wr + WO_M1PW, m1_pw_g, m1_pw_b, bufA, 256);
    gemm1x1<0,0><<<g1024, 256, SMEM>>>(bufA, nullptr, 256, 0, wr + WO_KV, nullptr, nullptr, kvb, 1024);
    dwconv<5, 0, 0><<<dim3(1024, NB), 256>>>(kvb, agg_kv_dw, nullptr, nullptr, kvtmp, 1024);
    grouped_pw<<<dim3(32, 32, NB), 256>>>(kvtmp, agg_kv_pw, kvsb, 1024);
    att_ctx<<<dim3(16, NB, 2 * NCH), 256>>>(kvb, kvsb, ctxpb);

    // ---- join, then attention output + m2 chain ----
    cudaStreamWaitEvent(0, evJoin, 0);
    att_out<<<dim3(32, 16, 2 * NB), 128>>>(qtb, qtsb, qrgbb, qrgbsb, ctxpb, attb);

    gemm1x1<0,1><<<g256, 256, SMEM>>>(attb, nullptr, 1024, 0, wr + WO_PROJ, nullptr, nullptr, bufA, 256);
    gemm1x1<1,0><<<g1024, 256, SMEM>>>(bufA, nullptr, 256, 0, wr + WO_M2INV, nullptr, m2_inv_bias, kvtmp, 1024);
    dwconv<3, 1, 1><<<dim3(1024, NB), 256>>>(kvtmp, m2_dw_w, nullptr, m2_dw_bias, kvsb, 1024);
    gemm1x1<0,0><<<g256, 256, SMEM>>>(kvsb, nullptr, 1024, 0, wr + WO_M2PW, m2_pw_g, m2_pw_b, (float*)d_out, 256);
}